// round 5
// baseline (speedup 1.0000x reference)
#include <cuda_runtime.h>
#include <cuda_bf16.h>
#include <cstdint>

// Problem constants
#define NN 50000
#define EE 500000
#define RR 8
#define HD 128
#define NG 64
#define NC 16
#define MT 64
#define NT64 ((NN + 63) / 64)      // 782

// ---------------- scratch (device globals; no allocs allowed) ----------------
__device__ __align__(16) __nv_bfloat16 g_xwb[(size_t)NN * 1024];  // messages, bf16
__device__ float g_hacc0[(size_t)NN * HD];     // layer-1 accumulator
__device__ float g_hacc1[(size_t)NN * HD];     // layer-2 accumulator
__device__ __align__(16) __nv_bfloat16 g_wh[9 * 128 * 128];  // weight hi, [ct][n][k]
__device__ __align__(16) __nv_bfloat16 g_wl[9 * 128 * 128];  // weight lo, [ct][n][k]
__device__ int   g_cnt[NN * RR];
__device__ float g_pool[NG * HD];
__device__ float g_pcnt[NG];

// ---------------- helpers ----------------
__device__ __forceinline__ uint32_t smem_to_u32(const void* p) {
    uint32_t a;
    asm("{ .reg .u64 t; cvta.to.shared.u64 t, %1; cvt.u32.u64 %0, t; }" : "=r"(a) : "l"(p));
    return a;
}
__device__ __forceinline__ uint32_t pack_bf2(__nv_bfloat16 a, __nv_bfloat16 b) {
    __nv_bfloat162 t = __halves2bfloat162(a, b);
    return *reinterpret_cast<uint32_t*>(&t);
}
__device__ __forceinline__ void split_bf(float v, __nv_bfloat16& h, __nv_bfloat16& l) {
    h = __float2bfloat16(v);
    l = __float2bfloat16(v - __bfloat162float(h));
}
__device__ __forceinline__ void cp16(uint32_t dst, const void* src) {
    asm volatile("cp.async.cg.shared.global [%0], [%1], 16;" :: "r"(dst), "l"(src));
}
#define CP_COMMIT() asm volatile("cp.async.commit_group;" ::: "memory")
#define CP_WAIT(n)  asm volatile("cp.async.wait_group %0;" :: "n"(n) : "memory")

__device__ __forceinline__ void ldsm_x4(uint32_t addr, uint32_t& r0, uint32_t& r1,
                                        uint32_t& r2, uint32_t& r3) {
    asm volatile("ldmatrix.sync.aligned.m8n8.x4.shared.b16 {%0,%1,%2,%3}, [%4];"
                 : "=r"(r0), "=r"(r1), "=r"(r2), "=r"(r3) : "r"(addr));
}
__device__ __forceinline__ void mma16816(float* c, const uint32_t* a, const uint32_t* b) {
    asm volatile("mma.sync.aligned.m16n8k16.row.col.f32.bf16.bf16.f32 "
                 "{%0,%1,%2,%3}, {%4,%5,%6,%7}, {%8,%9}, {%0,%1,%2,%3};"
                 : "+f"(c[0]), "+f"(c[1]), "+f"(c[2]), "+f"(c[3])
                 : "r"(a[0]), "r"(a[1]), "r"(a[2]), "r"(a[3]), "r"(b[0]), "r"(b[1]));
}

// smem layout (bytes): padded rows 136 bf16 = 272 B
#define ROWB 272
#define SM_A_HI 0
#define SM_A_LO 17408               // 64*272
#define SM_B_HI 34816
#define SM_B_LO 69632               // 34816 + 128*272
#define SMEM_TOTAL 104448           // 34816 + 2*34816

// ---------------- small utility kernels ----------------
__global__ void zero_int_kernel(int n) {
    int i = blockIdx.x * blockDim.x + threadIdx.x;
    if (i < n) g_cnt[i] = 0;
}
__global__ void zero_pool_kernel() {
    int i = blockIdx.x * blockDim.x + threadIdx.x;
    if (i < NG * HD) g_pool[i] = 0.0f;
    if (i < NG) g_pcnt[i] = 0.0f;
}
__global__ void count_kernel(const int* __restrict__ dst, const int* __restrict__ rel) {
    int e = blockIdx.x * blockDim.x + threadIdx.x;
    if (e < EE) atomicAdd(&g_cnt[dst[e] * RR + rel[e]], 1);
}

// pack weights: split fp32 -> bf16 hi/lo, layout [ct][n][k] (col-major for mma row.col)
__global__ void pack_w_kernel(const float* __restrict__ W, const float* __restrict__ root) {
    int i = blockIdx.x * blockDim.x + threadIdx.x;
    if (i >= 9 * 128 * 128) return;
    int ct = i >> 14;
    int rem = i & 16383;
    int n = rem >> 7;
    int k = rem & 127;
    float v = (ct < 8) ? W[((size_t)ct * 128 + k) * 128 + n] : root[(size_t)k * 128 + n];
    __nv_bfloat16 h, l;
    split_bf(v, h, l);
    g_wh[i] = h;
    g_wl[i] = l;
}

// ---------------- mma.sync split-bf16 GEMM: A[M,128] @ Wcat[128,1152] ----------------
// M-tile 64, 2 CTAs/SM; B single buffer pipelined by k-halves.
__global__ __launch_bounds__(256, 2)
void gemm_mma_kernel(const float* __restrict__ x_in, const float* __restrict__ bias, int layer) {
    extern __shared__ char smem[];
    const float* __restrict__ A = (layer == 0) ? x_in : g_hacc0;
    float* __restrict__ outroot = (layer == 0) ? g_hacc0 : g_hacc1;
    const bool relu = (layer != 0);

    const int tid = threadIdx.x;
    const int wid = tid >> 5, lane = tid & 31;
    const int warp_m = wid >> 2;          // 0..1  (32 rows each)
    const int warp_n = wid & 3;           // 0..3  (32 cols each)
    const int mt = blockIdx.x;
    const uint32_t su = smem_to_u32(smem);

    // per-lane ldmatrix byte offsets
    const uint32_t a_lane = (uint32_t)(warp_m * 32 + ((lane >> 3) & 1) * 8 + (lane & 7)) * ROWB
                          + (uint32_t)(lane >> 4) * 16;
    const uint32_t b_lane = (uint32_t)(warp_n * 32 + ((lane >> 4) & 1) * 8 + (lane & 7)) * ROWB
                          + (uint32_t)((lane >> 3) & 1) * 16;

    // bias pairs for ct==8 epilogue
    float2 bv[4];
    #pragma unroll
    for (int ni = 0; ni < 4; ni++)
        bv[ni] = *(const float2*)(bias + warp_n * 32 + ni * 8 + (lane & 3) * 2);

    // ---- load + split A tile (once per block): 64 rows x 128 k ----
    {
        int row = tid >> 2;
        int kh = (tid & 3) * 32;
        int m = mt * MT + row;
        const float* ap = A + (size_t)m * 128 + kh;
        char* dh = smem + SM_A_HI + row * ROWB + kh * 2;
        char* dl = smem + SM_A_LO + row * ROWB + kh * 2;
        #pragma unroll
        for (int j = 0; j < 8; j++) {
            float4 v = make_float4(0.f, 0.f, 0.f, 0.f);
            if (m < NN) v = *(const float4*)(ap + 4 * j);
            if (relu) {
                v.x = fmaxf(v.x, 0.f); v.y = fmaxf(v.y, 0.f);
                v.z = fmaxf(v.z, 0.f); v.w = fmaxf(v.w, 0.f);
            }
            __nv_bfloat16 h0, l0, h1, l1, h2, l2, h3, l3;
            split_bf(v.x, h0, l0); split_bf(v.y, h1, l1);
            split_bf(v.z, h2, l2); split_bf(v.w, h3, l3);
            *(uint32_t*)(dh + 8 * j)     = pack_bf2(h0, h1);
            *(uint32_t*)(dh + 8 * j + 4) = pack_bf2(h2, h3);
            *(uint32_t*)(dl + 8 * j)     = pack_bf2(l0, l1);
            *(uint32_t*)(dl + 8 * j + 4) = pack_bf2(l2, l3);
        }
    }

    // B half prefetch: half = 128 n-rows x 64 k, hi+lo. thread: n = tid&127, part = tid>>7
    #define PREFETCH_B_HALF(ct_, half_) do {                                          \
        int n_ = tid & 127, part_ = tid >> 7;                                         \
        const __nv_bfloat16* src_ = (part_ ? g_wl : g_wh)                             \
            + (size_t)(ct_) * 16384 + n_ * 128 + (half_) * 64;                        \
        uint32_t dst_ = su + (part_ ? SM_B_LO : SM_B_HI) + n_ * ROWB + (half_) * 128; \
        _Pragma("unroll")                                                             \
        for (int j_ = 0; j_ < 8; j_++) cp16(dst_ + 16 * j_, (const char*)src_ + 16 * j_); \
        CP_COMMIT();                                                                  \
    } while (0)

    PREFETCH_B_HALF(0, 0);
    PREFETCH_B_HALF(0, 1);

    float c[2][4][4];
    uint32_t ah[2][2][4], al[2][2][4], bh[2][4][2], bl[2][4][2];

    const uint32_t as_h = su + SM_A_HI + a_lane;
    const uint32_t as_l = su + SM_A_LO + a_lane;
    const uint32_t bs_h = su + SM_B_HI + b_lane;
    const uint32_t bs_l = su + SM_B_LO + b_lane;

    // fragment-load: slot s, byte k-offset
    #define LOAD_FRAGS(s, koff) do {                                                  \
        _Pragma("unroll")                                                             \
        for (int mi = 0; mi < 2; mi++)                                                \
            ldsm_x4(as_h + mi * (16 * ROWB) + (koff),                                 \
                    ah[s][mi][0], ah[s][mi][1], ah[s][mi][2], ah[s][mi][3]);          \
        _Pragma("unroll")                                                             \
        for (int mi = 0; mi < 2; mi++)                                                \
            ldsm_x4(as_l + mi * (16 * ROWB) + (koff),                                 \
                    al[s][mi][0], al[s][mi][1], al[s][mi][2], al[s][mi][3]);          \
        _Pragma("unroll")                                                             \
        for (int p = 0; p < 2; p++) {                                                 \
            uint32_t r0, r1, r2, r3;                                                  \
            ldsm_x4(bs_h + p * (16 * ROWB) + (koff), r0, r1, r2, r3);                 \
            bh[s][2 * p][0] = r0; bh[s][2 * p][1] = r1;                               \
            bh[s][2 * p + 1][0] = r2; bh[s][2 * p + 1][1] = r3;                       \
        }                                                                             \
        _Pragma("unroll")                                                             \
        for (int p = 0; p < 2; p++) {                                                 \
            uint32_t r0, r1, r2, r3;                                                  \
            ldsm_x4(bs_l + p * (16 * ROWB) + (koff), r0, r1, r2, r3);                 \
            bl[s][2 * p][0] = r0; bl[s][2 * p][1] = r1;                               \
            bl[s][2 * p + 1][0] = r2; bl[s][2 * p + 1][1] = r3;                       \
        }                                                                             \
    } while (0)

    #define COMPUTE_HALF(halfbyte) do {                                               \
        LOAD_FRAGS(0, (halfbyte));                                                    \
        _Pragma("unroll")                                                             \
        for (int k0 = 0; k0 < 4; k0++) {                                              \
            const int cur = k0 & 1;                                                   \
            if (k0 < 3) LOAD_FRAGS(cur ^ 1, (halfbyte) + (uint32_t)(k0 + 1) * 32u);   \
            _Pragma("unroll")                                                         \
            for (int mi = 0; mi < 2; mi++)                                            \
                _Pragma("unroll")                                                     \
                for (int ni = 0; ni < 4; ni++) {                                      \
                    mma16816(c[mi][ni], ah[cur][mi], bh[cur][ni]);                    \
                    mma16816(c[mi][ni], ah[cur][mi], bl[cur][ni]);                    \
                    mma16816(c[mi][ni], al[cur][mi], bh[cur][ni]);                    \
                }                                                                     \
        }                                                                             \
    } while (0)

    for (int ct = 0; ct < 9; ct++) {
        #pragma unroll
        for (int mi = 0; mi < 2; mi++)
            #pragma unroll
            for (int ni = 0; ni < 4; ni++)
                #pragma unroll
                for (int q = 0; q < 4; q++) c[mi][ni][q] = 0.0f;

        CP_WAIT(1);          // half0 of ct ready
        __syncthreads();
        COMPUTE_HALF(0u);

        CP_WAIT(0);          // half1 of ct ready
        __syncthreads();     // also: all warps done reading half0
        if (ct < 8) PREFETCH_B_HALF(ct + 1, 0);

        COMPUTE_HALF(128u);

        // ---- epilogue ----
        #pragma unroll
        for (int mi = 0; mi < 2; mi++) {
            int row0 = mt * MT + warp_m * 32 + mi * 16 + (lane >> 2);
            int row1 = row0 + 8;
            #pragma unroll
            for (int ni = 0; ni < 4; ni++) {
                int col = warp_n * 32 + ni * 8 + (lane & 3) * 2;
                if (ct < 8) {
                    if (row0 < NN)
                        *(uint32_t*)(g_xwb + (size_t)row0 * 1024 + ct * 128 + col) =
                            pack_bf2(__float2bfloat16(c[mi][ni][0]), __float2bfloat16(c[mi][ni][1]));
                    if (row1 < NN)
                        *(uint32_t*)(g_xwb + (size_t)row1 * 1024 + ct * 128 + col) =
                            pack_bf2(__float2bfloat16(c[mi][ni][2]), __float2bfloat16(c[mi][ni][3]));
                } else {
                    if (row0 < NN)
                        *(float2*)(outroot + (size_t)row0 * 128 + col) =
                            make_float2(c[mi][ni][0] + bv[ni].x, c[mi][ni][1] + bv[ni].y);
                    if (row1 < NN)
                        *(float2*)(outroot + (size_t)row1 * 128 + col) =
                            make_float2(c[mi][ni][2] + bv[ni].x, c[mi][ni][3] + bv[ni].y);
                }
            }
        }

        __syncthreads();     // all warps done reading half1 (+ epilogue)
        if (ct < 8) PREFETCH_B_HALF(ct + 1, 1);
    }
    #undef COMPUTE_HALF
    #undef LOAD_FRAGS
    #undef PREFETCH_B_HALF
}

// ---------------- edge aggregation: one warp per edge, bf16 gather + vector red ----------------
__global__ void edge_agg_kernel(const int* __restrict__ src, const int* __restrict__ dst,
                                const int* __restrict__ rel, int layer) {
    float* __restrict__ hacc = (layer == 0) ? g_hacc0 : g_hacc1;
    int gwarp = (blockIdx.x * blockDim.x + threadIdx.x) >> 5;
    int lane = threadIdx.x & 31;
    if (gwarp >= EE) return;
    int s = src[gwarp];
    int d = dst[gwarp];
    int r = rel[gwarp];
    int c = g_cnt[d * RR + r];
    float coef = 1.0f / (float)max(c, 1);
    const uint2 raw = *(const uint2*)(g_xwb + (size_t)s * 1024 + r * 128 + lane * 4);
    float2 p0 = __bfloat1622float2(*reinterpret_cast<const __nv_bfloat162*>(&raw.x));
    float2 p1 = __bfloat1622float2(*reinterpret_cast<const __nv_bfloat162*>(&raw.y));
    float* o = hacc + (size_t)d * 128 + lane * 4;
    asm volatile("red.global.add.v4.f32 [%0], {%1, %2, %3, %4};"
                 :: "l"(o), "f"(p0.x * coef), "f"(p0.y * coef), "f"(p1.x * coef), "f"(p1.y * coef)
                 : "memory");
}

// ---------------- pooling: sum relu(h2) per graph ----------------
__global__ void pool_kernel(const int* __restrict__ batch) {
    int i = blockIdx.x * blockDim.x + threadIdx.x;
    if (i >= NN * HD) return;
    int n = i >> 7, h = i & 127;
    float v = fmaxf(g_hacc1[i], 0.0f);
    int g = batch[n];
    asm volatile("red.global.add.f32 [%0], %1;" :: "l"(&g_pool[g * HD + h]), "f"(v) : "memory");
    if (h == 0)
        asm volatile("red.global.add.f32 [%0], %1;" :: "l"(&g_pcnt[g]), "f"(1.0f) : "memory");
}

// ---------------- head ----------------
__global__ void final_kernel(const float* __restrict__ linW, const float* __restrict__ linb,
                             float* __restrict__ out) {
    int g = blockIdx.x;
    int tid = threadIdx.x;  // 128
    __shared__ float p[HD];
    float cnt = fmaxf(g_pcnt[g], 1.0f);
    p[tid] = g_pool[g * HD + tid] / cnt;
    __syncthreads();
    if (tid < NC) {
        float s = linb[tid];
        #pragma unroll 8
        for (int h = 0; h < HD; h++) s = fmaf(p[h], linW[h * NC + tid], s);
        out[g * NC + tid] = s;
    }
}

// ---------------- launch ----------------
extern "C" void kernel_launch(void* const* d_in, const int* in_sizes, int n_in,
                              void* d_out, int out_size) {
    const float* x     = (const float*)d_in[0];
    const int*   eidx  = (const int*)d_in[1];
    const int*   etype = (const int*)d_in[2];
    const int*   batch = (const int*)d_in[3];
    const float* W1    = (const float*)d_in[4];
    const float* root1 = (const float*)d_in[5];
    const float* b1    = (const float*)d_in[6];
    const float* W2    = (const float*)d_in[7];
    const float* root2 = (const float*)d_in[8];
    const float* b2    = (const float*)d_in[9];
    const float* linW  = (const float*)d_in[10];
    const float* linb  = (const float*)d_in[11];
    float* out = (float*)d_out;

    const int* src = eidx;
    const int* dst = eidx + EE;

    static bool attr_done = false;
    if (!attr_done) {
        cudaFuncSetAttribute(gemm_mma_kernel, cudaFuncAttributeMaxDynamicSharedMemorySize, SMEM_TOTAL);
        attr_done = true;
    }

    // structure-dependent counts (shared by both layers)
    zero_int_kernel<<<(NN * RR + 255) / 256, 256>>>(NN * RR);
    count_kernel<<<(EE + 255) / 256, 256>>>(dst, etype);

    int edge_blocks = (EE * 32 + 255) / 256;
    int pack_blocks = (9 * 128 * 128 + 255) / 256;

    // layer 1
    pack_w_kernel<<<pack_blocks, 256>>>(W1, root1);
    gemm_mma_kernel<<<NT64, 256, SMEM_TOTAL>>>(x, b1, 0);
    edge_agg_kernel<<<edge_blocks, 256>>>(src, dst, etype, 0);

    // layer 2 (relu of layer-1 fused into GEMM A-load)
    pack_w_kernel<<<pack_blocks, 256>>>(W2, root2);
    gemm_mma_kernel<<<NT64, 256, SMEM_TOTAL>>>(x, b2, 1);
    edge_agg_kernel<<<edge_blocks, 256>>>(src, dst, etype, 1);

    // pooling + head (relu of layer-2 fused into pooling read)
    zero_pool_kernel<<<(NG * HD + 255) / 256, 256>>>();
    pool_kernel<<<(NN * HD + 255) / 256, 256>>>(batch);
    final_kernel<<<NG, 128>>>(linW, linb, out);
}

// round 6
// speedup vs baseline: 1.4352x; 1.4352x over previous
#include <cuda_runtime.h>
#include <cuda_bf16.h>
#include <cstdint>

// Problem constants
#define NN 50000
#define EE 500000
#define RR 8
#define HD 128
#define NG 64
#define NC 16
#define NTILES ((NN + 127) / 128)   // 391

// ---------------- scratch (device globals; no allocs allowed) ----------------
__device__ __align__(16) __nv_bfloat16 g_xwb[(size_t)NN * 1024];  // messages, bf16
__device__ float g_hacc0[(size_t)NN * HD];     // layer-1 accumulator
__device__ float g_hacc1[(size_t)NN * HD];     // layer-2 accumulator
__device__ __align__(16) __nv_bfloat16 g_wh[9 * 128 * 128];  // weight hi, [ct][n][k]
__device__ __align__(16) __nv_bfloat16 g_wl[9 * 128 * 128];  // weight lo, [ct][n][k]
__device__ int   g_cnt[NN * RR];
__device__ float g_pool[NG * HD];
__device__ float g_pcnt[NG];

// ---------------- helpers ----------------
__device__ __forceinline__ uint32_t smem_to_u32(const void* p) {
    uint32_t a;
    asm("{ .reg .u64 t; cvta.to.shared.u64 t, %1; cvt.u32.u64 %0, t; }" : "=r"(a) : "l"(p));
    return a;
}
__device__ __forceinline__ uint32_t pack_bf2(__nv_bfloat16 a, __nv_bfloat16 b) {
    __nv_bfloat162 t = __halves2bfloat162(a, b);
    return *reinterpret_cast<uint32_t*>(&t);
}
__device__ __forceinline__ void split_bf(float v, __nv_bfloat16& h, __nv_bfloat16& l) {
    h = __float2bfloat16(v);
    l = __float2bfloat16(v - __bfloat162float(h));
}
__device__ __forceinline__ void cp16(uint32_t dst, const void* src) {
    asm volatile("cp.async.cg.shared.global [%0], [%1], 16;" :: "r"(dst), "l"(src));
}
#define CP_COMMIT() asm volatile("cp.async.commit_group;" ::: "memory")
#define CP_WAIT(n)  asm volatile("cp.async.wait_group %0;" :: "n"(n) : "memory")

__device__ __forceinline__ void ldsm_x4(uint32_t addr, uint32_t& r0, uint32_t& r1,
                                        uint32_t& r2, uint32_t& r3) {
    asm volatile("ldmatrix.sync.aligned.m8n8.x4.shared.b16 {%0,%1,%2,%3}, [%4];"
                 : "=r"(r0), "=r"(r1), "=r"(r2), "=r"(r3) : "r"(addr));
}
__device__ __forceinline__ void mma16816(float* c, const uint32_t* a, const uint32_t* b) {
    asm volatile("mma.sync.aligned.m16n8k16.row.col.f32.bf16.bf16.f32 "
                 "{%0,%1,%2,%3}, {%4,%5,%6,%7}, {%8,%9}, {%0,%1,%2,%3};"
                 : "+f"(c[0]), "+f"(c[1]), "+f"(c[2]), "+f"(c[3])
                 : "r"(a[0]), "r"(a[1]), "r"(a[2]), "r"(a[3]), "r"(b[0]), "r"(b[1]));
}

// smem layout (bytes): padded rows 136 bf16 = 272 B; tile = 128*272 = 34816
#define ROWB 272
#define TILEB 34816
#define SM_A_HI 0
#define SM_A_LO 34816
#define SM_BH0  69632
#define SM_BH1  104448
#define SM_BL   139264
#define SMEM_TOTAL 174080

// ---------------- small utility kernels ----------------
__global__ void zero_int_kernel(int n) {
    int i = blockIdx.x * blockDim.x + threadIdx.x;
    if (i < n) g_cnt[i] = 0;
}
__global__ void zero_pool_kernel() {
    int i = blockIdx.x * blockDim.x + threadIdx.x;
    if (i < NG * HD) g_pool[i] = 0.0f;
    if (i < NG) g_pcnt[i] = 0.0f;
}
__global__ void count_kernel(const int* __restrict__ dst, const int* __restrict__ rel) {
    int e = blockIdx.x * blockDim.x + threadIdx.x;
    if (e < EE) atomicAdd(&g_cnt[dst[e] * RR + rel[e]], 1);
}

// pack weights: split fp32 -> bf16 hi/lo, layout [ct][n][k] (col-major for mma row.col)
__global__ void pack_w_kernel(const float* __restrict__ W, const float* __restrict__ root) {
    int i = blockIdx.x * blockDim.x + threadIdx.x;
    if (i >= 9 * 128 * 128) return;
    int ct = i >> 14;
    int rem = i & 16383;
    int n = rem >> 7;
    int k = rem & 127;
    float v = (ct < 8) ? W[((size_t)ct * 128 + k) * 128 + n] : root[(size_t)k * 128 + n];
    __nv_bfloat16 h, l;
    split_bf(v, h, l);
    g_wh[i] = h;
    g_wl[i] = l;
}

// ---------------- mma.sync GEMM: A[M,128] @ Wcat[128,1152] ----------------
// Relation cts 0..7: single-pass bf16 (messages, stored bf16).
// Root ct 8: fused 3-pass split-bf16 (fp32-quality) + bias -> hacc.
__global__ __launch_bounds__(256, 1)
void gemm_mma_kernel(const float* __restrict__ x_in, const float* __restrict__ bias, int layer) {
    extern __shared__ char smem[];
    const float* __restrict__ A = (layer == 0) ? x_in : g_hacc0;
    float* __restrict__ outroot = (layer == 0) ? g_hacc0 : g_hacc1;
    const bool relu = (layer != 0);

    const int tid = threadIdx.x;
    const int wid = tid >> 5, lane = tid & 31;
    const int warp_m = wid >> 2;          // 0..1  (64 rows each)
    const int warp_n = wid & 3;           // 0..3  (32 cols each)
    const int mt = blockIdx.x;
    const uint32_t su = smem_to_u32(smem);

    // per-lane ldmatrix byte offsets
    const uint32_t a_lane = (uint32_t)(warp_m * 64 + ((lane >> 3) & 1) * 8 + (lane & 7)) * ROWB
                          + (uint32_t)(lane >> 4) * 16;
    const uint32_t b_lane = (uint32_t)(warp_n * 32 + ((lane >> 4) & 1) * 8 + (lane & 7)) * ROWB
                          + (uint32_t)((lane >> 3) & 1) * 16;

    // bias pairs for ct==8 epilogue
    float2 bv[4];
    #pragma unroll
    for (int ni = 0; ni < 4; ni++)
        bv[ni] = *(const float2*)(bias + warp_n * 32 + ni * 8 + (lane & 3) * 2);

    // ---- load + split A tile (once per block) ----
    {
        int row = tid >> 1;
        int kh = (tid & 1) * 64;
        int m = mt * 128 + row;
        const float* ap = A + (size_t)m * 128 + kh;
        char* dh = smem + SM_A_HI + row * ROWB + kh * 2;
        char* dl = smem + SM_A_LO + row * ROWB + kh * 2;
        #pragma unroll
        for (int j = 0; j < 16; j++) {
            float4 v = make_float4(0.f, 0.f, 0.f, 0.f);
            if (m < NN) v = *(const float4*)(ap + 4 * j);
            if (relu) {
                v.x = fmaxf(v.x, 0.f); v.y = fmaxf(v.y, 0.f);
                v.z = fmaxf(v.z, 0.f); v.w = fmaxf(v.w, 0.f);
            }
            __nv_bfloat16 h0, l0, h1, l1, h2, l2, h3, l3;
            split_bf(v.x, h0, l0); split_bf(v.y, h1, l1);
            split_bf(v.z, h2, l2); split_bf(v.w, h3, l3);
            *(uint32_t*)(dh + 8 * j)     = pack_bf2(h0, h1);
            *(uint32_t*)(dh + 8 * j + 4) = pack_bf2(h2, h3);
            *(uint32_t*)(dl + 8 * j)     = pack_bf2(l0, l1);
            *(uint32_t*)(dl + 8 * j + 4) = pack_bf2(l2, l3);
        }
    }

    // full-tile prefetch: 256 threads x 128B
    #define PF_TILE(gsrc, ct_, smoff) do {                                            \
        int n_ = tid >> 1, half_ = tid & 1;                                           \
        const char* s_ = (const char*)((gsrc) + (size_t)(ct_) * 16384 + n_ * 128 + half_ * 64); \
        uint32_t d_ = su + (smoff) + n_ * ROWB + half_ * 128;                         \
        _Pragma("unroll")                                                             \
        for (int j_ = 0; j_ < 8; j_++) cp16(d_ + 16 * j_, s_ + 16 * j_);              \
    } while (0)

    PF_TILE(g_wh, 0, SM_BH0);
    CP_COMMIT();

    const uint32_t as_h = su + SM_A_HI + a_lane;
    const uint32_t as_l = su + SM_A_LO + a_lane;
    const uint32_t bs_l = su + SM_BL + b_lane;

    // fragment loads (base address parametrized)
    #define LOAD_A4(dst, base, koff) do {                                             \
        _Pragma("unroll")                                                             \
        for (int mi = 0; mi < 4; mi++)                                                \
            ldsm_x4((base) + mi * (16 * ROWB) + (koff),                               \
                    dst[mi][0], dst[mi][1], dst[mi][2], dst[mi][3]);                  \
    } while (0)
    #define LOAD_B4(dst, base, koff) do {                                             \
        _Pragma("unroll")                                                             \
        for (int p = 0; p < 2; p++) {                                                 \
            uint32_t r0, r1, r2, r3;                                                  \
            ldsm_x4((base) + p * (16 * ROWB) + (koff), r0, r1, r2, r3);               \
            dst[2 * p][0] = r0; dst[2 * p][1] = r1;                                   \
            dst[2 * p + 1][0] = r2; dst[2 * p + 1][1] = r3;                           \
        }                                                                             \
    } while (0)

    for (int ct = 0; ct < 9; ct++) {
        const uint32_t bs_h = su + ((ct & 1) ? SM_BH1 : SM_BH0) + b_lane;

        if (ct < 8) {
            PF_TILE(g_wh, ct + 1, (ct & 1) ? SM_BH0 : SM_BH1);
            if (ct == 7) PF_TILE(g_wl, 8, SM_BL);
            CP_COMMIT();
            CP_WAIT(1);
        } else {
            CP_WAIT(0);
        }
        __syncthreads();

        float c[4][4][4];
        #pragma unroll
        for (int mi = 0; mi < 4; mi++)
            #pragma unroll
            for (int ni = 0; ni < 4; ni++)
                #pragma unroll
                for (int q = 0; q < 4; q++) c[mi][ni][q] = 0.0f;

        if (ct < 8) {
            // ---- single-pass bf16: messages ----
            uint32_t ah[2][4][4], bh[2][4][2];
            LOAD_A4(ah[0], as_h, 0u);
            LOAD_B4(bh[0], bs_h, 0u);
            #pragma unroll
            for (int k0 = 0; k0 < 8; k0++) {
                const int cur = k0 & 1;
                if (k0 < 7) {
                    LOAD_A4(ah[cur ^ 1], as_h, (uint32_t)(k0 + 1) * 32u);
                    LOAD_B4(bh[cur ^ 1], bs_h, (uint32_t)(k0 + 1) * 32u);
                }
                #pragma unroll
                for (int mi = 0; mi < 4; mi++)
                    #pragma unroll
                    for (int ni = 0; ni < 4; ni++)
                        mma16816(c[mi][ni], ah[cur][mi], bh[cur][ni]);
            }
            // epilogue: bf16 messages
            #pragma unroll
            for (int mi = 0; mi < 4; mi++) {
                int row0 = mt * 128 + warp_m * 64 + mi * 16 + (lane >> 2);
                int row1 = row0 + 8;
                #pragma unroll
                for (int ni = 0; ni < 4; ni++) {
                    int col = warp_n * 32 + ni * 8 + (lane & 3) * 2;
                    if (row0 < NN)
                        *(uint32_t*)(g_xwb + (size_t)row0 * 1024 + ct * 128 + col) =
                            pack_bf2(__float2bfloat16(c[mi][ni][0]), __float2bfloat16(c[mi][ni][1]));
                    if (row1 < NN)
                        *(uint32_t*)(g_xwb + (size_t)row1 * 1024 + ct * 128 + col) =
                            pack_bf2(__float2bfloat16(c[mi][ni][2]), __float2bfloat16(c[mi][ni][3]));
                }
            }
        } else {
            // ---- fused 3-pass split-bf16: root + bias ----
            uint32_t ah[2][4][4], al[2][4][4], bh[2][4][2], bl[2][4][2];
            LOAD_A4(ah[0], as_h, 0u); LOAD_A4(al[0], as_l, 0u);
            LOAD_B4(bh[0], bs_h, 0u); LOAD_B4(bl[0], bs_l, 0u);
            #pragma unroll
            for (int k0 = 0; k0 < 8; k0++) {
                const int cur = k0 & 1;
                if (k0 < 7) {
                    const uint32_t koff = (uint32_t)(k0 + 1) * 32u;
                    LOAD_A4(ah[cur ^ 1], as_h, koff); LOAD_A4(al[cur ^ 1], as_l, koff);
                    LOAD_B4(bh[cur ^ 1], bs_h, koff); LOAD_B4(bl[cur ^ 1], bs_l, koff);
                }
                #pragma unroll
                for (int mi = 0; mi < 4; mi++)
                    #pragma unroll
                    for (int ni = 0; ni < 4; ni++) {
                        mma16816(c[mi][ni], ah[cur][mi], bh[cur][ni]);
                        mma16816(c[mi][ni], ah[cur][mi], bl[cur][ni]);
                        mma16816(c[mi][ni], al[cur][mi], bh[cur][ni]);
                    }
            }
            // epilogue: fp32 + bias
            #pragma unroll
            for (int mi = 0; mi < 4; mi++) {
                int row0 = mt * 128 + warp_m * 64 + mi * 16 + (lane >> 2);
                int row1 = row0 + 8;
                #pragma unroll
                for (int ni = 0; ni < 4; ni++) {
                    int col = warp_n * 32 + ni * 8 + (lane & 3) * 2;
                    if (row0 < NN)
                        *(float2*)(outroot + (size_t)row0 * 128 + col) =
                            make_float2(c[mi][ni][0] + bv[ni].x, c[mi][ni][1] + bv[ni].y);
                    if (row1 < NN)
                        *(float2*)(outroot + (size_t)row1 * 128 + col) =
                            make_float2(c[mi][ni][2] + bv[ni].x, c[mi][ni][3] + bv[ni].y);
                }
            }
        }

        __syncthreads();
    }
    #undef LOAD_A4
    #undef LOAD_B4
    #undef PF_TILE
}

// ---------------- edge aggregation: one warp per edge, bf16 gather + vector red ----------------
__global__ void edge_agg_kernel(const int* __restrict__ src, const int* __restrict__ dst,
                                const int* __restrict__ rel, int layer) {
    float* __restrict__ hacc = (layer == 0) ? g_hacc0 : g_hacc1;
    int gwarp = (blockIdx.x * blockDim.x + threadIdx.x) >> 5;
    int lane = threadIdx.x & 31;
    if (gwarp >= EE) return;
    int s = src[gwarp];
    int d = dst[gwarp];
    int r = rel[gwarp];
    int c = g_cnt[d * RR + r];
    float coef = 1.0f / (float)max(c, 1);
    const uint2 raw = *(const uint2*)(g_xwb + (size_t)s * 1024 + r * 128 + lane * 4);
    float2 p0 = __bfloat1622float2(*reinterpret_cast<const __nv_bfloat162*>(&raw.x));
    float2 p1 = __bfloat1622float2(*reinterpret_cast<const __nv_bfloat162*>(&raw.y));
    float* o = hacc + (size_t)d * 128 + lane * 4;
    asm volatile("red.global.add.v4.f32 [%0], {%1, %2, %3, %4};"
                 :: "l"(o), "f"(p0.x * coef), "f"(p0.y * coef), "f"(p1.x * coef), "f"(p1.y * coef)
                 : "memory");
}

// ---------------- pooling: sum relu(h2) per graph ----------------
__global__ void pool_kernel(const int* __restrict__ batch) {
    int i = blockIdx.x * blockDim.x + threadIdx.x;
    if (i >= NN * HD) return;
    int n = i >> 7, h = i & 127;
    float v = fmaxf(g_hacc1[i], 0.0f);
    int g = batch[n];
    asm volatile("red.global.add.f32 [%0], %1;" :: "l"(&g_pool[g * HD + h]), "f"(v) : "memory");
    if (h == 0)
        asm volatile("red.global.add.f32 [%0], %1;" :: "l"(&g_pcnt[g]), "f"(1.0f) : "memory");
}

// ---------------- head ----------------
__global__ void final_kernel(const float* __restrict__ linW, const float* __restrict__ linb,
                             float* __restrict__ out) {
    int g = blockIdx.x;
    int tid = threadIdx.x;  // 128
    __shared__ float p[HD];
    float cnt = fmaxf(g_pcnt[g], 1.0f);
    p[tid] = g_pool[g * HD + tid] / cnt;
    __syncthreads();
    if (tid < NC) {
        float s = linb[tid];
        #pragma unroll 8
        for (int h = 0; h < HD; h++) s = fmaf(p[h], linW[h * NC + tid], s);
        out[g * NC + tid] = s;
    }
}

// ---------------- launch ----------------
extern "C" void kernel_launch(void* const* d_in, const int* in_sizes, int n_in,
                              void* d_out, int out_size) {
    const float* x     = (const float*)d_in[0];
    const int*   eidx  = (const int*)d_in[1];
    const int*   etype = (const int*)d_in[2];
    const int*   batch = (const int*)d_in[3];
    const float* W1    = (const float*)d_in[4];
    const float* root1 = (const float*)d_in[5];
    const float* b1    = (const float*)d_in[6];
    const float* W2    = (const float*)d_in[7];
    const float* root2 = (const float*)d_in[8];
    const float* b2    = (const float*)d_in[9];
    const float* linW  = (const float*)d_in[10];
    const float* linb  = (const float*)d_in[11];
    float* out = (float*)d_out;

    const int* src = eidx;
    const int* dst = eidx + EE;

    static bool attr_done = false;
    if (!attr_done) {
        cudaFuncSetAttribute(gemm_mma_kernel, cudaFuncAttributeMaxDynamicSharedMemorySize, SMEM_TOTAL);
        attr_done = true;
    }

    // structure-dependent counts (shared by both layers)
    zero_int_kernel<<<(NN * RR + 255) / 256, 256>>>(NN * RR);
    count_kernel<<<(EE + 255) / 256, 256>>>(dst, etype);

    int edge_blocks = (EE * 32 + 255) / 256;
    int pack_blocks = (9 * 128 * 128 + 255) / 256;

    // layer 1
    pack_w_kernel<<<pack_blocks, 256>>>(W1, root1);
    gemm_mma_kernel<<<NTILES, 256, SMEM_TOTAL>>>(x, b1, 0);
    edge_agg_kernel<<<edge_blocks, 256>>>(src, dst, etype, 0);

    // layer 2 (relu of layer-1 fused into GEMM A-load)
    pack_w_kernel<<<pack_blocks, 256>>>(W2, root2);
    gemm_mma_kernel<<<NTILES, 256, SMEM_TOTAL>>>(x, b2, 1);
    edge_agg_kernel<<<edge_blocks, 256>>>(src, dst, etype, 1);

    // pooling + head (relu of layer-2 fused into pooling read)
    zero_pool_kernel<<<(NG * HD + 255) / 256, 256>>>();
    pool_kernel<<<(NN * HD + 255) / 256, 256>>>(batch);
    final_kernel<<<NG, 128>>>(linW, linb, out);
}

// round 7
// speedup vs baseline: 1.8685x; 1.3019x over previous
#include <cuda_runtime.h>
#include <cuda_bf16.h>
#include <cstdint>

// Problem constants
#define NN 50000
#define EE 500000
#define RR 8
#define HD 128
#define NG 64
#define NC 16
#define NTILES ((NN + 127) / 128)   // 391
#define NBLK ((NN + 255) / 256)     // 196

// ---------------- scratch (device globals; no allocs allowed) ----------------
__device__ __align__(16) __nv_bfloat16 g_xwb[(size_t)NN * 1024];  // messages, bf16
__device__ float g_hacc0[(size_t)NN * HD];     // layer-1 accumulator
__device__ float g_hacc1[(size_t)NN * HD];     // layer-2 accumulator
__device__ __align__(16) __nv_bfloat16 g_wh[9 * 128 * 128];  // weight hi, [ct][n][k]
__device__ __align__(16) __nv_bfloat16 g_wl[9 * 128 * 128];  // weight lo, [ct][n][k]
__device__ int   g_cnt[NN * RR];               // per (dst, rel) counts
__device__ int   g_ncnt[NN];                   // per dst counts
__device__ int   g_off[NN];                    // CSR offsets
__device__ int   g_cur[NN];                    // scatter cursors
__device__ int   g_bsum[256];                  // block sums for scan
__device__ int   g_bbase[256];                 // scanned block bases
__device__ int2  g_edges[EE];                  // dst-sorted: {src*8+rel, coef bits}
__device__ float g_pool[NG * HD];
__device__ float g_pcnt[NG];

// ---------------- helpers ----------------
__device__ __forceinline__ uint32_t smem_to_u32(const void* p) {
    uint32_t a;
    asm("{ .reg .u64 t; cvta.to.shared.u64 t, %1; cvt.u32.u64 %0, t; }" : "=r"(a) : "l"(p));
    return a;
}
__device__ __forceinline__ uint32_t pack_bf2(__nv_bfloat16 a, __nv_bfloat16 b) {
    __nv_bfloat162 t = __halves2bfloat162(a, b);
    return *reinterpret_cast<uint32_t*>(&t);
}
__device__ __forceinline__ void split_bf(float v, __nv_bfloat16& h, __nv_bfloat16& l) {
    h = __float2bfloat16(v);
    l = __float2bfloat16(v - __bfloat162float(h));
}
__device__ __forceinline__ void cp16(uint32_t dst, const void* src) {
    asm volatile("cp.async.cg.shared.global [%0], [%1], 16;" :: "r"(dst), "l"(src));
}
#define CP_COMMIT() asm volatile("cp.async.commit_group;" ::: "memory")
#define CP_WAIT(n)  asm volatile("cp.async.wait_group %0;" :: "n"(n) : "memory")

__device__ __forceinline__ void ldsm_x4(uint32_t addr, uint32_t& r0, uint32_t& r1,
                                        uint32_t& r2, uint32_t& r3) {
    asm volatile("ldmatrix.sync.aligned.m8n8.x4.shared.b16 {%0,%1,%2,%3}, [%4];"
                 : "=r"(r0), "=r"(r1), "=r"(r2), "=r"(r3) : "r"(addr));
}
__device__ __forceinline__ void mma16816(float* c, const uint32_t* a, const uint32_t* b) {
    asm volatile("mma.sync.aligned.m16n8k16.row.col.f32.bf16.bf16.f32 "
                 "{%0,%1,%2,%3}, {%4,%5,%6,%7}, {%8,%9}, {%0,%1,%2,%3};"
                 : "+f"(c[0]), "+f"(c[1]), "+f"(c[2]), "+f"(c[3])
                 : "r"(a[0]), "r"(a[1]), "r"(a[2]), "r"(a[3]), "r"(b[0]), "r"(b[1]));
}

// smem layout (bytes): padded rows 136 bf16 = 272 B; tile = 128*272 = 34816
#define ROWB 272
#define SM_A_HI 0
#define SM_A_LO 34816
#define SM_BH0  69632
#define SM_BH1  104448
#define SM_BL   139264
#define SMEM_TOTAL 174080

// ---------------- structure kernels ----------------
__global__ void zero_kernel() {
    int i = blockIdx.x * blockDim.x + threadIdx.x;
    if (i < NN * RR) g_cnt[i] = 0;
    if (i < NN) g_ncnt[i] = 0;
    if (i < NG * HD) g_pool[i] = 0.0f;
    if (i < NG) g_pcnt[i] = 0.0f;
}
__global__ void count_kernel(const int* __restrict__ dst, const int* __restrict__ rel) {
    int e = blockIdx.x * blockDim.x + threadIdx.x;
    if (e < EE) {
        int d = dst[e];
        atomicAdd(&g_cnt[d * RR + rel[e]], 1);
        atomicAdd(&g_ncnt[d], 1);
    }
}
__global__ void pcnt_kernel(const int* __restrict__ batch) {
    int i = blockIdx.x * blockDim.x + threadIdx.x;
    if (i < NN)
        asm volatile("red.global.add.f32 [%0], %1;" :: "l"(&g_pcnt[batch[i]]), "f"(1.0f) : "memory");
}
__global__ void scan_bsum_kernel() {
    __shared__ int s[256];
    int i = blockIdx.x * 256 + threadIdx.x;
    int t = threadIdx.x;
    s[t] = (i < NN) ? g_ncnt[i] : 0;
    __syncthreads();
    for (int st = 128; st > 0; st >>= 1) {
        if (t < st) s[t] += s[t + st];
        __syncthreads();
    }
    if (t == 0) g_bsum[blockIdx.x] = s[0];
}
__global__ void scan_base_kernel() {   // single block, 256 threads
    __shared__ int s[256];
    int t = threadIdx.x;
    int v = (t < NBLK) ? g_bsum[t] : 0;
    s[t] = v;
    __syncthreads();
    for (int st = 1; st < 256; st <<= 1) {
        int add = (t >= st) ? s[t - st] : 0;
        __syncthreads();
        s[t] += add;
        __syncthreads();
    }
    if (t < NBLK) g_bbase[t] = s[t] - v;
}
__global__ void scan_final_kernel() {
    __shared__ int s[256];
    int i = blockIdx.x * 256 + threadIdx.x;
    int t = threadIdx.x;
    int v = (i < NN) ? g_ncnt[i] : 0;
    s[t] = v;
    __syncthreads();
    for (int st = 1; st < 256; st <<= 1) {
        int add = (t >= st) ? s[t - st] : 0;
        __syncthreads();
        s[t] += add;
        __syncthreads();
    }
    if (i < NN) {
        int off = g_bbase[blockIdx.x] + s[t] - v;
        g_off[i] = off;
        g_cur[i] = off;
    }
}
__global__ void scatter_kernel(const int* __restrict__ src, const int* __restrict__ dst,
                               const int* __restrict__ rel) {
    int e = blockIdx.x * blockDim.x + threadIdx.x;
    if (e >= EE) return;
    int d = dst[e], r = rel[e];
    int c = g_cnt[d * RR + r];
    float coef = 1.0f / (float)max(c, 1);
    int pos = atomicAdd(&g_cur[d], 1);
    g_edges[pos] = make_int2(src[e] * 8 + r, __float_as_int(coef));
}

// pack weights: split fp32 -> bf16 hi/lo, layout [ct][n][k] (col-major for mma row.col)
__global__ void pack_w_kernel(const float* __restrict__ W, const float* __restrict__ root) {
    int i = blockIdx.x * blockDim.x + threadIdx.x;
    if (i >= 9 * 128 * 128) return;
    int ct = i >> 14;
    int rem = i & 16383;
    int n = rem >> 7;
    int k = rem & 127;
    float v = (ct < 8) ? W[((size_t)ct * 128 + k) * 128 + n] : root[(size_t)k * 128 + n];
    __nv_bfloat16 h, l;
    split_bf(v, h, l);
    g_wh[i] = h;
    g_wl[i] = l;
}

// ---------------- mma.sync GEMM: A[M,128] @ Wcat[128,1152] ----------------
// Relation cts 0..7: single-pass bf16 (messages, stored bf16).
// Root ct 8: fused 3-pass split-bf16 (fp32-quality) + bias -> hacc.
__global__ __launch_bounds__(256, 1)
void gemm_mma_kernel(const float* __restrict__ x_in, const float* __restrict__ bias, int layer) {
    extern __shared__ char smem[];
    const float* __restrict__ A = (layer == 0) ? x_in : g_hacc0;
    float* __restrict__ outroot = (layer == 0) ? g_hacc0 : g_hacc1;
    const bool relu = (layer != 0);

    const int tid = threadIdx.x;
    const int wid = tid >> 5, lane = tid & 31;
    const int warp_m = wid >> 2;
    const int warp_n = wid & 3;
    const int mt = blockIdx.x;
    const uint32_t su = smem_to_u32(smem);

    const uint32_t a_lane = (uint32_t)(warp_m * 64 + ((lane >> 3) & 1) * 8 + (lane & 7)) * ROWB
                          + (uint32_t)(lane >> 4) * 16;
    const uint32_t b_lane = (uint32_t)(warp_n * 32 + ((lane >> 4) & 1) * 8 + (lane & 7)) * ROWB
                          + (uint32_t)((lane >> 3) & 1) * 16;

    float2 bv[4];
    #pragma unroll
    for (int ni = 0; ni < 4; ni++)
        bv[ni] = *(const float2*)(bias + warp_n * 32 + ni * 8 + (lane & 3) * 2);

    // ---- load + split A tile (once per block) ----
    {
        int row = tid >> 1;
        int kh = (tid & 1) * 64;
        int m = mt * 128 + row;
        const float* ap = A + (size_t)m * 128 + kh;
        char* dh = smem + SM_A_HI + row * ROWB + kh * 2;
        char* dl = smem + SM_A_LO + row * ROWB + kh * 2;
        #pragma unroll
        for (int j = 0; j < 16; j++) {
            float4 v = make_float4(0.f, 0.f, 0.f, 0.f);
            if (m < NN) v = *(const float4*)(ap + 4 * j);
            if (relu) {
                v.x = fmaxf(v.x, 0.f); v.y = fmaxf(v.y, 0.f);
                v.z = fmaxf(v.z, 0.f); v.w = fmaxf(v.w, 0.f);
            }
            __nv_bfloat16 h0, l0, h1, l1, h2, l2, h3, l3;
            split_bf(v.x, h0, l0); split_bf(v.y, h1, l1);
            split_bf(v.z, h2, l2); split_bf(v.w, h3, l3);
            *(uint32_t*)(dh + 8 * j)     = pack_bf2(h0, h1);
            *(uint32_t*)(dh + 8 * j + 4) = pack_bf2(h2, h3);
            *(uint32_t*)(dl + 8 * j)     = pack_bf2(l0, l1);
            *(uint32_t*)(dl + 8 * j + 4) = pack_bf2(l2, l3);
        }
    }

    #define PF_TILE(gsrc, ct_, smoff) do {                                            \
        int n_ = tid >> 1, half_ = tid & 1;                                           \
        const char* s_ = (const char*)((gsrc) + (size_t)(ct_) * 16384 + n_ * 128 + half_ * 64); \
        uint32_t d_ = su + (smoff) + n_ * ROWB + half_ * 128;                         \
        _Pragma("unroll")                                                             \
        for (int j_ = 0; j_ < 8; j_++) cp16(d_ + 16 * j_, s_ + 16 * j_);              \
    } while (0)

    PF_TILE(g_wh, 0, SM_BH0);
    CP_COMMIT();

    const uint32_t as_h = su + SM_A_HI + a_lane;
    const uint32_t as_l = su + SM_A_LO + a_lane;
    const uint32_t bs_l = su + SM_BL + b_lane;

    #define LOAD_A4(dst, base, koff) do {                                             \
        _Pragma("unroll")                                                             \
        for (int mi = 0; mi < 4; mi++)                                                \
            ldsm_x4((base) + mi * (16 * ROWB) + (koff),                               \
                    dst[mi][0], dst[mi][1], dst[mi][2], dst[mi][3]);                  \
    } while (0)
    #define LOAD_B4(dst, base, koff) do {                                             \
        _Pragma("unroll")                                                             \
        for (int p = 0; p < 2; p++) {                                                 \
            uint32_t r0, r1, r2, r3;                                                  \
            ldsm_x4((base) + p * (16 * ROWB) + (koff), r0, r1, r2, r3);               \
            dst[2 * p][0] = r0; dst[2 * p][1] = r1;                                   \
            dst[2 * p + 1][0] = r2; dst[2 * p + 1][1] = r3;                           \
        }                                                                             \
    } while (0)

    for (int ct = 0; ct < 9; ct++) {
        const uint32_t bs_h = su + ((ct & 1) ? SM_BH1 : SM_BH0) + b_lane;

        if (ct < 8) {
            PF_TILE(g_wh, ct + 1, (ct & 1) ? SM_BH0 : SM_BH1);
            if (ct == 7) PF_TILE(g_wl, 8, SM_BL);
            CP_COMMIT();
            CP_WAIT(1);
        } else {
            CP_WAIT(0);
        }
        __syncthreads();

        float c[4][4][4];
        #pragma unroll
        for (int mi = 0; mi < 4; mi++)
            #pragma unroll
            for (int ni = 0; ni < 4; ni++)
                #pragma unroll
                for (int q = 0; q < 4; q++) c[mi][ni][q] = 0.0f;

        if (ct < 8) {
            uint32_t ah[2][4][4], bh[2][4][2];
            LOAD_A4(ah[0], as_h, 0u);
            LOAD_B4(bh[0], bs_h, 0u);
            #pragma unroll
            for (int k0 = 0; k0 < 8; k0++) {
                const int cur = k0 & 1;
                if (k0 < 7) {
                    LOAD_A4(ah[cur ^ 1], as_h, (uint32_t)(k0 + 1) * 32u);
                    LOAD_B4(bh[cur ^ 1], bs_h, (uint32_t)(k0 + 1) * 32u);
                }
                #pragma unroll
                for (int mi = 0; mi < 4; mi++)
                    #pragma unroll
                    for (int ni = 0; ni < 4; ni++)
                        mma16816(c[mi][ni], ah[cur][mi], bh[cur][ni]);
            }
            #pragma unroll
            for (int mi = 0; mi < 4; mi++) {
                int row0 = mt * 128 + warp_m * 64 + mi * 16 + (lane >> 2);
                int row1 = row0 + 8;
                #pragma unroll
                for (int ni = 0; ni < 4; ni++) {
                    int col = warp_n * 32 + ni * 8 + (lane & 3) * 2;
                    if (row0 < NN)
                        *(uint32_t*)(g_xwb + (size_t)row0 * 1024 + ct * 128 + col) =
                            pack_bf2(__float2bfloat16(c[mi][ni][0]), __float2bfloat16(c[mi][ni][1]));
                    if (row1 < NN)
                        *(uint32_t*)(g_xwb + (size_t)row1 * 1024 + ct * 128 + col) =
                            pack_bf2(__float2bfloat16(c[mi][ni][2]), __float2bfloat16(c[mi][ni][3]));
                }
            }
        } else {
            uint32_t ah[2][4][4], al[2][4][4], bh[2][4][2], bl[2][4][2];
            LOAD_A4(ah[0], as_h, 0u); LOAD_A4(al[0], as_l, 0u);
            LOAD_B4(bh[0], bs_h, 0u); LOAD_B4(bl[0], bs_l, 0u);
            #pragma unroll
            for (int k0 = 0; k0 < 8; k0++) {
                const int cur = k0 & 1;
                if (k0 < 7) {
                    const uint32_t koff = (uint32_t)(k0 + 1) * 32u;
                    LOAD_A4(ah[cur ^ 1], as_h, koff); LOAD_A4(al[cur ^ 1], as_l, koff);
                    LOAD_B4(bh[cur ^ 1], bs_h, koff); LOAD_B4(bl[cur ^ 1], bs_l, koff);
                }
                #pragma unroll
                for (int mi = 0; mi < 4; mi++)
                    #pragma unroll
                    for (int ni = 0; ni < 4; ni++) {
                        mma16816(c[mi][ni], ah[cur][mi], bh[cur][ni]);
                        mma16816(c[mi][ni], ah[cur][mi], bl[cur][ni]);
                        mma16816(c[mi][ni], al[cur][mi], bh[cur][ni]);
                    }
            }
            #pragma unroll
            for (int mi = 0; mi < 4; mi++) {
                int row0 = mt * 128 + warp_m * 64 + mi * 16 + (lane >> 2);
                int row1 = row0 + 8;
                #pragma unroll
                for (int ni = 0; ni < 4; ni++) {
                    int col = warp_n * 32 + ni * 8 + (lane & 3) * 2;
                    if (row0 < NN)
                        *(float2*)(outroot + (size_t)row0 * 128 + col) =
                            make_float2(c[mi][ni][0] + bv[ni].x, c[mi][ni][1] + bv[ni].y);
                    if (row1 < NN)
                        *(float2*)(outroot + (size_t)row1 * 128 + col) =
                            make_float2(c[mi][ni][2] + bv[ni].x, c[mi][ni][3] + bv[ni].y);
                }
            }
        }

        __syncthreads();
    }
    #undef LOAD_A4
    #undef LOAD_B4
    #undef PF_TILE
}

// ---------------- aggregation: one warp per dst node, no atomics ----------------
// layer 0: hacc0[d] += sum;  layer 1: pool[batch[d]] += relu(hacc1[d] + sum) (fused pooling)
__global__ void agg_kernel(const int* __restrict__ batch, int layer) {
    int node = (blockIdx.x * blockDim.x + threadIdx.x) >> 5;
    int lane = threadIdx.x & 31;
    if (node >= NN) return;
    int off = g_off[node];
    int n = g_ncnt[node];

    float ax = 0.f, ay = 0.f, az = 0.f, aw = 0.f;
    for (int i = 0; i < n; i++) {
        int2 er = __ldg(&g_edges[off + i]);
        float coef = __int_as_float(er.y);
        const uint2 raw = *(const uint2*)(g_xwb + (size_t)er.x * 128 + lane * 4);
        float2 p0 = __bfloat1622float2(*reinterpret_cast<const __nv_bfloat162*>(&raw.x));
        float2 p1 = __bfloat1622float2(*reinterpret_cast<const __nv_bfloat162*>(&raw.y));
        ax = fmaf(p0.x, coef, ax);
        ay = fmaf(p0.y, coef, ay);
        az = fmaf(p1.x, coef, az);
        aw = fmaf(p1.y, coef, aw);
    }

    if (layer == 0) {
        float4 h = *(float4*)(g_hacc0 + (size_t)node * 128 + lane * 4);
        h.x += ax; h.y += ay; h.z += az; h.w += aw;
        *(float4*)(g_hacc0 + (size_t)node * 128 + lane * 4) = h;
    } else {
        float4 h = *(float4*)(g_hacc1 + (size_t)node * 128 + lane * 4);
        h.x = fmaxf(h.x + ax, 0.f);
        h.y = fmaxf(h.y + ay, 0.f);
        h.z = fmaxf(h.z + az, 0.f);
        h.w = fmaxf(h.w + aw, 0.f);
        int g = __ldg(&batch[node]);
        float* o = g_pool + (size_t)g * HD + lane * 4;
        asm volatile("red.global.add.v4.f32 [%0], {%1, %2, %3, %4};"
                     :: "l"(o), "f"(h.x), "f"(h.y), "f"(h.z), "f"(h.w) : "memory");
    }
}

// ---------------- head ----------------
__global__ void final_kernel(const float* __restrict__ linW, const float* __restrict__ linb,
                             float* __restrict__ out) {
    int g = blockIdx.x;
    int tid = threadIdx.x;  // 128
    __shared__ float p[HD];
    float cnt = fmaxf(g_pcnt[g], 1.0f);
    p[tid] = g_pool[g * HD + tid] / cnt;
    __syncthreads();
    if (tid < NC) {
        float s = linb[tid];
        #pragma unroll 8
        for (int h = 0; h < HD; h++) s = fmaf(p[h], linW[h * NC + tid], s);
        out[g * NC + tid] = s;
    }
}

// ---------------- launch ----------------
extern "C" void kernel_launch(void* const* d_in, const int* in_sizes, int n_in,
                              void* d_out, int out_size) {
    const float* x     = (const float*)d_in[0];
    const int*   eidx  = (const int*)d_in[1];
    const int*   etype = (const int*)d_in[2];
    const int*   batch = (const int*)d_in[3];
    const float* W1    = (const float*)d_in[4];
    const float* root1 = (const float*)d_in[5];
    const float* b1    = (const float*)d_in[6];
    const float* W2    = (const float*)d_in[7];
    const float* root2 = (const float*)d_in[8];
    const float* b2    = (const float*)d_in[9];
    const float* linW  = (const float*)d_in[10];
    const float* linb  = (const float*)d_in[11];
    float* out = (float*)d_out;

    const int* src = eidx;
    const int* dst = eidx + EE;

    static bool attr_done = false;
    if (!attr_done) {
        cudaFuncSetAttribute(gemm_mma_kernel, cudaFuncAttributeMaxDynamicSharedMemorySize, SMEM_TOTAL);
        attr_done = true;
    }

    int pack_blocks = (9 * 128 * 128 + 255) / 256;
    int agg_blocks = (NN * 32 + 255) / 256;

    // ---- structure phase (once; shared by both layers) ----
    zero_kernel<<<(NN * RR + 255) / 256, 256>>>();
    count_kernel<<<(EE + 255) / 256, 256>>>(dst, etype);
    pcnt_kernel<<<(NN + 255) / 256, 256>>>(batch);
    scan_bsum_kernel<<<NBLK, 256>>>();
    scan_base_kernel<<<1, 256>>>();
    scan_final_kernel<<<NBLK, 256>>>();
    scatter_kernel<<<(EE + 255) / 256, 256>>>(src, dst, etype);
    // weights can pack concurrently-independent of structure
    pack_w_kernel<<<pack_blocks, 256>>>(W1, root1);

    // layer 1
    gemm_mma_kernel<<<NTILES, 256, SMEM_TOTAL>>>(x, b1, 0);
    agg_kernel<<<agg_blocks, 256>>>(batch, 0);

    // layer 2 (relu of layer-1 fused into GEMM A-load; relu+pool fused into agg)
    pack_w_kernel<<<pack_blocks, 256>>>(W2, root2);
    gemm_mma_kernel<<<NTILES, 256, SMEM_TOTAL>>>(x, b2, 1);
    agg_kernel<<<agg_blocks, 256>>>(batch, 1);

    final_kernel<<<NG, 128>>>(linW, linb, out);
}